// round 2
// baseline (speedup 1.0000x reference)
#include <cuda_runtime.h>
#include <cstdint>

#define CRF_B 512
#define CRF_S 512
#define CRF_T 64

// Per-batch partial results (device scratch; no allocations allowed).
__device__ float g_dpart[CRF_B];
__device__ float g_npart[CRF_B];

// Input-layout flags set by crf_detect (deterministic for fixed inputs).
__device__ int g_mshift;  // byte index of mask element = idx << g_mshift (0: u8, 2: i32)
__device__ int g_tshift;  // word index of tag element  = idx << g_tshift (0: i32, 1: i64)

typedef unsigned long long u64;

// ---- packed f32x2 helpers (sm_100+ PTX) ----
__device__ __forceinline__ u64 ffma2(u64 a, u64 b, u64 c) {
    u64 d;
    asm("fma.rn.f32x2 %0, %1, %2, %3;" : "=l"(d) : "l"(a), "l"(b), "l"(c));
    return d;
}
__device__ __forceinline__ u64 fadd2(u64 a, u64 b) {
    u64 d;
    asm("add.rn.f32x2 %0, %1, %2;" : "=l"(d) : "l"(a), "l"(b));
    return d;
}
__device__ __forceinline__ u64 pack2(float x, float y) {
    u64 d;
    asm("mov.b64 %0, {%1, %2};" : "=l"(d) : "f"(x), "f"(y));
    return d;
}
__device__ __forceinline__ float2 unpack2(u64 a) {
    float2 r;
    asm("mov.b64 {%0, %1}, %2;" : "=f"(r.x), "=f"(r.y) : "l"(a));
    return r;
}

// ============================================================================
// Detect the on-device layout of mask (u8 vs i32) and tags (i32 vs i64).
// mask: sample 64 leading words; any nonzero byte above byte0 => 1-byte layout.
// tags: values < 64 => if stored i64, every odd word is 0. Sample 16 odd words.
// ============================================================================
__global__ void crf_detect(const void* tags, const void* mask)
{
    if (threadIdx.x != 0) return;
    const unsigned* mw = (const unsigned*)mask;
    int m32 = 1;
    for (int i = 0; i < 64; i++) {
        if ((mw[i] & 0xFFFFFF00u) != 0u) { m32 = 0; break; }
    }
    g_mshift = m32 ? 2 : 0;

    const unsigned* tw = (const unsigned*)tags;
    int t64 = 1;
    for (int i = 1; i < 32; i += 2) {
        if (tw[i] != 0u) { t64 = 0; break; }
    }
    g_tshift = t64 ? 1 : 0;
}

// ============================================================================
// Forward (denominator) kernel: one block per batch, 64 threads (2 warps).
// Warp w reduces over i in [32w, 32w+32); thread lane l owns states j=2l,2l+1.
// E[i][j] = exp(trans[i][j]) lives in registers as f32x2 column pairs.
// p held in shared memory in duplicated form pdup[i] = {p_i, p_i} so that
// broadcast LDS.128 directly feeds fma.rn.f32x2 operands.
// ============================================================================
__global__ void __launch_bounds__(64) crf_forward(
    const float* __restrict__ logits,
    const void* __restrict__ maskv,
    const float* __restrict__ trans,
    const float* __restrict__ startT,
    const float* __restrict__ endT)
{
    const int b   = blockIdx.x;
    const int tid = threadIdx.x;
    const int w   = tid >> 5;
    const int l   = tid & 31;

    __shared__ __align__(16) u64 pdup[CRF_T];     // {p_i, p_i}
    __shared__ __align__(16) u64 part[2][32];     // per-warp partial sums (f32x2)

    // Load E column pair for this thread's i-range into registers.
    u64 Ereg[32];
#pragma unroll
    for (int k = 0; k < 32; k++) {
        const int i = 32 * w + k;
        float2 t = ((const float2*)trans)[i * 32 + l];
        Ereg[k] = pack2(__expf(t.x), __expf(t.y));
    }

    const int msh = g_mshift;
    const float*         lg = logits + (size_t)b * (CRF_S * CRF_T);
    const unsigned char* mk = (const unsigned char*)maskv + (((size_t)b * CRF_S) << msh);

    // alpha0 = start + logits[:,0,:]; convert to exp-domain with offset C.
    float2 l0 = ((const float2*)lg)[l];
    float a0 = startT[2 * l]     + l0.x;
    float a1 = startT[2 * l + 1] + l0.y;
    float mx = fmaxf(a0, a1);
#pragma unroll
    for (int o = 16; o; o >>= 1) mx = fmaxf(mx, __shfl_xor_sync(0xffffffffu, mx, o));
    float C  = mx;
    float p0 = __expf(a0 - mx);
    float p1 = __expf(a1 - mx);
    if (w == 0)
        ((ulonglong2*)pdup)[l] = make_ulonglong2(pack2(p0, p0), pack2(p1, p1));

    // Prefetch step-1 logits + mask.
    float2 nl        = ((const float2*)(lg + CRF_T))[l];
    unsigned char nm = mk[(size_t)1 << msh];
    __syncthreads();

    for (int s = 1; s < CRF_S; s++) {
        const float2 cl        = nl;
        const unsigned char cm = nm;
        if (s + 1 < CRF_S) {
            nl = ((const float2*)(lg + (size_t)(s + 1) * CRF_T))[l];
            nm = mk[(size_t)(s + 1) << msh];
        }

        // Partial GEMV over this warp's half of i (32 packed FMAs, 4 chains).
        const u64* pd = pdup + 32 * w;
        u64 acc0 = 0ull, acc1 = 0ull, acc2 = 0ull, acc3 = 0ull;
#pragma unroll
        for (int k = 0; k < 32; k += 4) {
            ulonglong2 q0 = *(const ulonglong2*)(pd + k);
            ulonglong2 q1 = *(const ulonglong2*)(pd + k + 2);
            acc0 = ffma2(Ereg[k + 0], q0.x, acc0);
            acc1 = ffma2(Ereg[k + 1], q0.y, acc1);
            acc2 = ffma2(Ereg[k + 2], q1.x, acc2);
            acc3 = ffma2(Ereg[k + 3], q1.y, acc3);
        }
        u64 accA = fadd2(fadd2(acc0, acc1), fadd2(acc2, acc3));
        part[w][l] = accA;
        __syncthreads();

        // Combine halves (commutative add -> both warps get bitwise-identical p).
        u64 tot    = fadd2(accA, part[1 - w][l]);
        float2 sum = unpack2(tot);
        float pn0 = sum.x * __expf(cl.x);
        float pn1 = sum.y * __expf(cl.y);
        if (cm) { p0 = pn0; p1 = pn1; }      // mask: keep old alpha if 0

        // Exact power-of-two renorm every 4 steps (overflow guard).
        if ((s & 3) == 0) {
            float m2 = fmaxf(p0, p1);
#pragma unroll
            for (int o = 16; o; o >>= 1)
                m2 = fmaxf(m2, __shfl_xor_sync(0xffffffffu, m2, o));
            int e = (__float_as_int(m2) >> 23) & 255;
            float scale = __int_as_float((254 - e) << 23);  // 2^(127-e)
            p0 *= scale;
            p1 *= scale;
            C += (float)(e - 127) * 0.6931471805599453f;
        }

        if (w == 0)
            ((ulonglong2*)pdup)[l] = make_ulonglong2(pack2(p0, p0), pack2(p1, p1));
        __syncthreads();
    }

    // denom = C + log(sum_j p_j * exp(end_j))
    if (w == 0) {
        float v = p0 * __expf(endT[2 * l]) + p1 * __expf(endT[2 * l + 1]);
#pragma unroll
        for (int o = 16; o; o >>= 1) v += __shfl_xor_sync(0xffffffffu, v, o);
        if (l == 0) g_dpart[b] = C + logf(v);
    }
}

// ============================================================================
// Numerator (gold-path score): one warp per batch; deterministic lane-strided
// sums + shfl tree reduction.
// ============================================================================
__global__ void crf_numerator(
    const float* __restrict__ logits,
    const void* __restrict__ tagsv,
    const void* __restrict__ maskv,
    const float* __restrict__ trans,
    const float* __restrict__ startT,
    const float* __restrict__ endT)
{
    const int gw = (blockIdx.x * blockDim.x + threadIdx.x) >> 5;
    const int l  = threadIdx.x & 31;
    if (gw >= CRF_B) return;

    const int msh = g_mshift;
    const int tsh = g_tshift;
    const int*           tg  = (const int*)tagsv;           // low word of each tag
    const unsigned char* mkp = (const unsigned char*)maskv;
    const float*         lg  = logits + (size_t)gw * (CRF_S * CRF_T);
    const size_t         eb  = (size_t)gw * CRF_S;          // element base

    float acc = 0.0f;
    int   cnt = 0;
    for (int s = l; s < CRF_S; s += 32) {
        const int  t = tg[(eb + s) << tsh];
        const bool m = (mkp[(eb + s) << msh] != 0);
        if (m) {
            cnt++;
            if (s < CRF_S - 1) acc += lg[(size_t)s * CRF_T + t];                      // emit, mask[:, :-1]
            if (s >= 1)        acc += trans[tg[(eb + s - 1) << tsh] * CRF_T + t];     // trans, mask[:, 1:]
        }
    }
#pragma unroll
    for (int o = 16; o; o >>= 1) {
        acc += __shfl_xor_sync(0xffffffffu, acc, o);
        cnt += __shfl_xor_sync(0xffffffffu, cnt, o);
    }
    if (l == 0) {
        acc += startT[tg[eb << tsh]];
        const int last = cnt - 1;
        const int lt   = tg[(eb + last) << tsh];
        acc += endT[lt];
        if (mkp[(eb + CRF_S - 1) << msh]) acc += lg[(size_t)(CRF_S - 1) * CRF_T + lt];
        g_npart[gw] = acc;
    }
}

// ============================================================================
// Final deterministic tree reduction: out = sum_b (num_b - denom_b)
// ============================================================================
__global__ void crf_reduce(float* __restrict__ out)
{
    __shared__ float buf[CRF_B];
    const int t = threadIdx.x;
    buf[t] = g_npart[t] - g_dpart[t];
    __syncthreads();
    for (int o = CRF_B / 2; o; o >>= 1) {
        if (t < o) buf[t] += buf[t + o];
        __syncthreads();
    }
    if (t == 0) out[0] = buf[0];
}

extern "C" void kernel_launch(void* const* d_in, const int* in_sizes, int n_in,
                              void* d_out, int out_size)
{
    const float* logits = (const float*)d_in[0];
    const void*  tags   = d_in[1];
    const void*  mask   = d_in[2];
    const float* trans  = (const float*)d_in[3];
    const float* startT = (const float*)d_in[4];
    const float* endT   = (const float*)d_in[5];
    float*       out    = (float*)d_out;

    crf_detect<<<1, 32>>>(tags, mask);
    crf_forward<<<CRF_B, 64>>>(logits, mask, trans, startT, endT);
    crf_numerator<<<CRF_B / 8, 256>>>(logits, tags, mask, trans, startT, endT);
    crf_reduce<<<1, CRF_B>>>(out);
}

// round 4
// speedup vs baseline: 1.5361x; 1.5361x over previous
#include <cuda_runtime.h>
#include <cstdint>

#define CRF_B 512
#define CRF_S 512
#define CRF_T 64

// Per-batch partial results (device scratch; no allocations allowed).
__device__ float g_dpart[CRF_B];
__device__ float g_npart[CRF_B];

typedef unsigned long long u64;

// ---- packed f32x2 helpers (sm_100+ PTX) ----
__device__ __forceinline__ u64 ffma2(u64 a, u64 b, u64 c) {
    u64 d;
    asm("fma.rn.f32x2 %0, %1, %2, %3;" : "=l"(d) : "l"(a), "l"(b), "l"(c));
    return d;
}
__device__ __forceinline__ u64 fadd2(u64 a, u64 b) {
    u64 d;
    asm("add.rn.f32x2 %0, %1, %2;" : "=l"(d) : "l"(a), "l"(b));
    return d;
}
__device__ __forceinline__ u64 pack2(float x, float y) {
    u64 d;
    asm("mov.b64 %0, {%1, %2};" : "=l"(d) : "f"(x), "f"(y));
    return d;
}
__device__ __forceinline__ float2 unpack2(u64 a) {
    float2 r;
    asm("mov.b64 {%0, %1}, %2;" : "=f"(r.x), "=f"(r.y) : "l"(a));
    return r;
}

// Warp-uniform layout detection (ballot => uniform result, no global state).
// mask: any nonzero high byte in first 64 words => 1-byte elements (shift 0),
//       else int32 elements (shift 2).
__device__ __forceinline__ int detect_mshift(const void* mask, int l) {
    const unsigned* mw = (const unsigned*)mask;
    unsigned bad = ((mw[l] | mw[l + 32]) & 0xFFFFFF00u) ? 1u : 0u;
    return __ballot_sync(0xffffffffu, bad) ? 0 : 2;
}
// tags: values < 64, so int64 storage => all odd 32-bit words zero.
__device__ __forceinline__ int detect_tshift(const void* tags, int l) {
    const unsigned* tw = (const unsigned*)tags;
    unsigned odd = tw[2 * l + 1] ? 1u : 0u;
    return __ballot_sync(0xffffffffu, odd) ? 0 : 1;
}

// ============================================================================
// Fused main kernel: 128 blocks x 160 threads.
//   Warps 0-3: forward recurrence (denominator), one batch per warp,
//              batch = 4*blockIdx.x + warp. No block-level barriers.
//   Warp 4:    numerator (gold-path score) for the block's 4 batches.
//
// Forward per-warp scheme: lane l owns states j=2l,2l+1. E=exp(trans) lives in
// registers (64 x f32x2). p held in per-warp ping-pong smem in duplicated form
// pdup[i]={p_i,p_i} so broadcast LDS.128 feeds fma.rn.f32x2 directly.
// Exp-domain recurrence with exact power-of-2 renorm every 4 steps.
// ============================================================================
__global__ void __launch_bounds__(160, 1) crf_main(
    const float* __restrict__ logits,
    const void* __restrict__ tagsv,
    const void* __restrict__ maskv,
    const float* __restrict__ trans,
    const float* __restrict__ startT,
    const float* __restrict__ endT)
{
    __shared__ __align__(16) u64 pdup[4][2][CRF_T];

    const int tid = threadIdx.x;
    const int w   = tid >> 5;
    const int l   = tid & 31;

    // ---------------- Numerator warp ----------------
    if (w == 4) {
        const int msh = detect_mshift(maskv, l);
        const int tsh = detect_tshift(tagsv, l);
        const int*           tg  = (const int*)tagsv;
        const unsigned char* mkp = (const unsigned char*)maskv;

        for (int q = 0; q < 4; q++) {
            const int    b  = blockIdx.x * 4 + q;
            const float* lg = logits + (size_t)b * (CRF_S * CRF_T);
            const size_t eb = (size_t)b * CRF_S;

            float acc = 0.0f;
            int   cnt = 0;
            for (int s = l; s < CRF_S; s += 32) {
                const int  t = tg[(eb + s) << tsh];
                const bool m = (mkp[(eb + s) << msh] != 0);
                if (m) {
                    cnt++;
                    if (s < CRF_S - 1) acc += lg[(size_t)s * CRF_T + t];
                    if (s >= 1)        acc += trans[tg[(eb + s - 1) << tsh] * CRF_T + t];
                }
            }
#pragma unroll
            for (int o = 16; o; o >>= 1) {
                acc += __shfl_xor_sync(0xffffffffu, acc, o);
                cnt += __shfl_xor_sync(0xffffffffu, cnt, o);
            }
            if (l == 0) {
                acc += startT[tg[eb << tsh]];
                const int lt = tg[(eb + cnt - 1) << tsh];
                acc += endT[lt];
                if (mkp[(eb + CRF_S - 1) << msh]) acc += lg[(size_t)(CRF_S - 1) * CRF_T + lt];
                g_npart[b] = acc;
            }
        }
        return;
    }

    // ---------------- Forward warps ----------------
    const int msh = detect_mshift(maskv, l);
    const int b   = blockIdx.x * 4 + w;

    // E column pair for this lane, all 64 rows, in registers.
    u64 Ereg[64];
#pragma unroll
    for (int i = 0; i < 64; i++) {
        float2 t = ((const float2*)trans)[i * 32 + l];
        Ereg[i] = pack2(__expf(t.x), __expf(t.y));
    }

    const float*         lg = logits + (size_t)b * (CRF_S * CRF_T);
    const unsigned char* mk = (const unsigned char*)maskv + (((size_t)b * CRF_S) << msh);

    // exp(end) for the epilogue.
    const float ee0 = __expf(endT[2 * l]);
    const float ee1 = __expf(endT[2 * l + 1]);

    // alpha0 = start + logits[:,0,:]; to exp-domain with offset C.
    float2 l0 = ((const float2*)lg)[l];
    float a0 = startT[2 * l]     + l0.x;
    float a1 = startT[2 * l + 1] + l0.y;
    float mx = fmaxf(a0, a1);
#pragma unroll
    for (int o = 16; o; o >>= 1) mx = fmaxf(mx, __shfl_xor_sync(0xffffffffu, mx, o));
    float C  = mx;
    float p0 = __expf(a0 - mx);
    float p1 = __expf(a1 - mx);
    ((ulonglong2*)pdup[w][0])[l] = make_ulonglong2(pack2(p0, p0), pack2(p1, p1));

    // Prologue: prime a 4-deep logits/mask register FIFO (rows s+1..s+4 at s=1)
    // and the exp of the current row (s=1).
    float2 f1 = ((const float2*)(lg + 1 * CRF_T))[l];
    float2 f2 = ((const float2*)(lg + 2 * CRF_T))[l];
    float2 f3 = ((const float2*)(lg + 3 * CRF_T))[l];
    float2 f4 = ((const float2*)(lg + 4 * CRF_T))[l];
    float2 f5 = ((const float2*)(lg + 5 * CRF_T))[l];
    unsigned char m1 = mk[(size_t)1 << msh];
    unsigned char m2 = mk[(size_t)2 << msh];
    unsigned char m3 = mk[(size_t)3 << msh];
    unsigned char m4 = mk[(size_t)4 << msh];
    unsigned char m5 = mk[(size_t)5 << msh];
    float e0 = __expf(f1.x);
    float e1 = __expf(f1.y);
    unsigned char cm = m1;
    __syncwarp();

    for (int s = 1; s < CRF_S; s++) {
        // Rotate FIFO; issue load for row s+5; start exp for row s+1 (off path).
        const float2 head = f2;
        const unsigned char mh = m2;
        f2 = f3; m2 = m3;
        f3 = f4; m3 = m4;
        f4 = f5; m4 = m5;
        if (s + 5 < CRF_S) {
            f5 = ((const float2*)(lg + (size_t)(s + 5) * CRF_T))[l];
            m5 = mk[(size_t)(s + 5) << msh];
        }
        const float ne0 = __expf(head.x);
        const float ne1 = __expf(head.y);

        // GEMV over all 64 states: 32 broadcast LDS.128, 64 FFMA2, 8 chains.
        const ulonglong2* pd2 = (const ulonglong2*)pdup[w][(s - 1) & 1];
        u64 a0v = 0ull, a1v = 0ull, a2v = 0ull, a3v = 0ull;
        u64 a4v = 0ull, a5v = 0ull, a6v = 0ull, a7v = 0ull;
#pragma unroll
        for (int k = 0; k < 64; k += 8) {
            ulonglong2 q0 = pd2[(k >> 1) + 0];
            ulonglong2 q1 = pd2[(k >> 1) + 1];
            ulonglong2 q2 = pd2[(k >> 1) + 2];
            ulonglong2 q3 = pd2[(k >> 1) + 3];
            a0v = ffma2(Ereg[k + 0], q0.x, a0v);
            a1v = ffma2(Ereg[k + 1], q0.y, a1v);
            a2v = ffma2(Ereg[k + 2], q1.x, a2v);
            a3v = ffma2(Ereg[k + 3], q1.y, a3v);
            a4v = ffma2(Ereg[k + 4], q2.x, a4v);
            a5v = ffma2(Ereg[k + 5], q2.y, a5v);
            a6v = ffma2(Ereg[k + 6], q3.x, a6v);
            a7v = ffma2(Ereg[k + 7], q3.y, a7v);
        }
        u64 tot = fadd2(fadd2(fadd2(a0v, a1v), fadd2(a2v, a3v)),
                        fadd2(fadd2(a4v, a5v), fadd2(a6v, a7v)));
        float2 sum = unpack2(tot);
        if (cm) {                       // mask: keep old alpha if 0
            p0 = sum.x * e0;
            p1 = sum.y * e1;
        }

        // Exact power-of-two renorm every 4 steps (overflow guard).
        // Scale from lane 0's exponent (single shfl): alpha spread is bounded,
        // only magnitude containment is required; scaling is exact in fp.
        if ((s & 3) == 0) {
            int e = (__float_as_int(p0) >> 23) & 255;
            e = __shfl_sync(0xffffffffu, e, 0);
            float scale = __int_as_float((254 - e) << 23);   // 2^(127-e)
            p0 *= scale;
            p1 *= scale;
            C += (float)(e - 127) * 0.6931471805599453f;
        }

        ((ulonglong2*)pdup[w][s & 1])[l] =
            make_ulonglong2(pack2(p0, p0), pack2(p1, p1));
        e0 = ne0; e1 = ne1; cm = mh;
        __syncwarp();
    }

    // denom = C + log(sum_j p_j * exp(end_j))
    float v = p0 * ee0 + p1 * ee1;
#pragma unroll
    for (int o = 16; o; o >>= 1) v += __shfl_xor_sync(0xffffffffu, v, o);
    if (l == 0) g_dpart[b] = C + logf(v);
}

// ============================================================================
// Final deterministic tree reduction: out = sum_b (num_b - denom_b)
// ============================================================================
__global__ void crf_reduce(float* __restrict__ out)
{
    __shared__ float buf[CRF_B];
    const int t = threadIdx.x;
    buf[t] = g_npart[t] - g_dpart[t];
    __syncthreads();
    for (int o = CRF_B / 2; o; o >>= 1) {
        if (t < o) buf[t] += buf[t + o];
        __syncthreads();
    }
    if (t == 0) out[0] = buf[0];
}

extern "C" void kernel_launch(void* const* d_in, const int* in_sizes, int n_in,
                              void* d_out, int out_size)
{
    const float* logits = (const float*)d_in[0];
    const void*  tags   = d_in[1];
    const void*  mask   = d_in[2];
    const float* trans  = (const float*)d_in[3];
    const float* startT = (const float*)d_in[4];
    const float* endT   = (const float*)d_in[5];
    float*       out    = (float*)d_out;

    crf_main<<<CRF_B / 4, 160>>>(logits, tags, mask, trans, startT, endT);
    crf_reduce<<<1, CRF_B>>>(out);
}